// round 7
// baseline (speedup 1.0000x reference)
#include <cuda_runtime.h>
#include <cuda_bf16.h>

// DurationCalculator:
//   weights_argmax[b,y] = duration[b,y] + (y < output_length[b] ? 0 : -10000)
//   durations[b,x]      = count over y of (weights_argmax[b,y] == x), 0 <= x < X
// Output (float32): [ weights_argmax (B*Y) | durations (B*X) ]
//
// One CTA per row. Histogram done entirely with global L2 atomics (REDG):
//   1) CTA zeroes its exclusive h_out row via atomicExch (L2 ops)
//   2) __syncthreads (fence.cta: zero happens-before the adds)
//   3) streaming pass: LDG.128 -> mask-add -> STG.128 + REDG.ADD.F32 per valid elem
// No shared memory, no merge phase, single kernel node.

#ifndef MASK_PENALTY
#define MASK_PENALTY (-10000)
#endif

__global__ void __launch_bounds__(512)
duration_calc_kernel(const int* __restrict__ duration,
                     const int* __restrict__ output_length,
                     float* __restrict__ w_out,
                     float* __restrict__ h_out,
                     int Y, int X)
{
    const int b   = blockIdx.x;
    const int tid = threadIdx.x;
    const int nt  = blockDim.x;   // 512

    float* __restrict__ hrow = h_out + (size_t)b * X;

    // Zero this row's histogram with L2 atomics. Row is exclusively owned by
    // this CTA, and the barrier below (fence.cta) orders these before the
    // REDG.ADDs issued after it.
    for (int i = tid; i < X; i += nt) atomicExch(&hrow[i], 0.0f);
    __syncthreads();

    const int L = output_length[b];

    const int4* __restrict__ dur4 = reinterpret_cast<const int4*>(duration + (size_t)b * Y);
    float4* __restrict__ w4       = reinterpret_cast<float4*>(w_out + (size_t)b * Y);
    const int n4 = Y >> 2;        // 1024 for Y=4096

    #pragma unroll 2
    for (int i = tid; i < n4; i += nt) {
        const int y = i << 2;
        int4 d = dur4[i];
        int wx = d.x + ((y + 0) < L ? 0 : MASK_PENALTY);
        int wy = d.y + ((y + 1) < L ? 0 : MASK_PENALTY);
        int wz = d.z + ((y + 2) < L ? 0 : MASK_PENALTY);
        int ww = d.w + ((y + 3) < L ? 0 : MASK_PENALTY);
        float4 w;
        w.x = (float)wx; w.y = (float)wy; w.z = (float)wz; w.w = (float)ww;
        w4[i] = w;
        // unsigned compare folds (w >= 0 && w < X); masked entries negative.
        // Return value unused -> fire-and-forget REDG at L2.
        if ((unsigned)wx < (unsigned)X) atomicAdd(&hrow[wx], 1.0f);
        if ((unsigned)wy < (unsigned)X) atomicAdd(&hrow[wy], 1.0f);
        if ((unsigned)wz < (unsigned)X) atomicAdd(&hrow[wz], 1.0f);
        if ((unsigned)ww < (unsigned)X) atomicAdd(&hrow[ww], 1.0f);
    }

    // Scalar tail for Y not a multiple of 4 (no-op for Y=4096)
    for (int y = (n4 << 2) + tid; y < Y; y += nt) {
        int w = duration[(size_t)b * Y + y] + (y < L ? 0 : MASK_PENALTY);
        w_out[(size_t)b * Y + y] = (float)w;
        if ((unsigned)w < (unsigned)X) atomicAdd(&hrow[w], 1.0f);
    }
}

extern "C" void kernel_launch(void* const* d_in, const int* in_sizes, int n_in,
                              void* d_out, int out_size)
{
    const int* duration      = (const int*)d_in[0];
    const int* output_length = (const int*)d_in[1];

    const int B = in_sizes[1];          // 256
    const int Y = in_sizes[0] / B;      // 4096
    const int X = out_size / B - Y;     // 1024

    float* w_out = (float*)d_out;                   // weights_argmax: B*Y
    float* h_out = (float*)d_out + (size_t)B * Y;   // durations:      B*X

    const int threads = 512;
    duration_calc_kernel<<<B, threads>>>(duration, output_length,
                                         w_out, h_out, Y, X);
}

// round 9
// speedup vs baseline: 1.2657x; 1.2657x over previous
#include <cuda_runtime.h>
#include <cuda_bf16.h>

// DurationCalculator:
//   weights_argmax[b,y] = duration[b,y] + (y < output_length[b] ? 0 : -10000)
//   durations[b,x]      = count over y of (weights_argmax[b,y] == x), 0 <= x < X
// Output (float32): [ weights_argmax (B*Y) | durations (B*X) ]
//
// One CTA per row, 512 threads. Hybrid histogram: even warps accumulate into a
// shared-memory histogram (ATOMS pipe), odd warps fire REDG.ADD.F32 directly at
// the CTA-exclusive global row (LTS atomic pipe). Global row zeroed in-kernel
// with plain stores; __syncthreads (fence.cta) orders them before this CTA's
// REDGs. smem partials merged into global at the end via REDG.

#ifndef MASK_PENALTY
#define MASK_PENALTY (-10000)
#endif

__global__ void __launch_bounds__(512)
duration_calc_kernel(const int* __restrict__ duration,
                     const int* __restrict__ output_length,
                     float* __restrict__ w_out,
                     float* __restrict__ h_out,
                     int Y, int X)
{
    extern __shared__ int hist[];  // X bins
    const int b   = blockIdx.x;
    const int tid = threadIdx.x;
    const int nt  = blockDim.x;    // 512
    const int wid = tid >> 5;

    float* __restrict__ hrow = h_out + (size_t)b * X;

    // Zero smem histogram and (exclusively-owned) global row.
    for (int i = tid; i < X; i += nt) hist[i] = 0;
    {
        float4 z = make_float4(0.f, 0.f, 0.f, 0.f);
        float4* __restrict__ hrow4 = reinterpret_cast<float4*>(hrow);
        for (int i = tid; i < (X >> 2); i += nt) hrow4[i] = z;
    }
    __syncthreads();   // fence.cta: zeros happen-before our REDGs below

    const int L = output_length[b];

    const int4* __restrict__ dur4 = reinterpret_cast<const int4*>(duration + (size_t)b * Y);
    float4* __restrict__ w4       = reinterpret_cast<float4*>(w_out + (size_t)b * Y);
    const int n4 = Y >> 2;         // 1024 for Y=4096

    const bool use_smem = (wid & 1) == 0;   // warp-granularity pipe routing

    for (int i = tid; i < n4; i += nt) {
        const int y = i << 2;
        int4 d = dur4[i];
        int wx = d.x + ((y + 0) < L ? 0 : MASK_PENALTY);
        int wy = d.y + ((y + 1) < L ? 0 : MASK_PENALTY);
        int wz = d.z + ((y + 2) < L ? 0 : MASK_PENALTY);
        int ww = d.w + ((y + 3) < L ? 0 : MASK_PENALTY);
        float4 w;
        w.x = (float)wx; w.y = (float)wy; w.z = (float)wz; w.w = (float)ww;
        w4[i] = w;
        // unsigned compare folds (w >= 0 && w < X); masked entries negative.
        if (use_smem) {
            if ((unsigned)wx < (unsigned)X) atomicAdd(&hist[wx], 1);
            if ((unsigned)wy < (unsigned)X) atomicAdd(&hist[wy], 1);
            if ((unsigned)wz < (unsigned)X) atomicAdd(&hist[wz], 1);
            if ((unsigned)ww < (unsigned)X) atomicAdd(&hist[ww], 1);
        } else {
            if ((unsigned)wx < (unsigned)X) atomicAdd(&hrow[wx], 1.0f);  // REDG
            if ((unsigned)wy < (unsigned)X) atomicAdd(&hrow[wy], 1.0f);
            if ((unsigned)wz < (unsigned)X) atomicAdd(&hrow[wz], 1.0f);
            if ((unsigned)ww < (unsigned)X) atomicAdd(&hrow[ww], 1.0f);
        }
    }

    // Scalar tail for Y not a multiple of 4 (no-op for Y=4096)
    for (int y = (n4 << 2) + tid; y < Y; y += nt) {
        int w = duration[(size_t)b * Y + y] + (y < L ? 0 : MASK_PENALTY);
        w_out[(size_t)b * Y + y] = (float)w;
        if ((unsigned)w < (unsigned)X) atomicAdd(&hist[w], 1);
    }

    __syncthreads();

    // Merge smem partials into global row (exact: small integer-valued fp32).
    for (int i = tid; i < X; i += nt) {
        int c = hist[i];
        if (c) atomicAdd(&hrow[i], (float)c);
    }
}

extern "C" void kernel_launch(void* const* d_in, const int* in_sizes, int n_in,
                              void* d_out, int out_size)
{
    const int* duration      = (const int*)d_in[0];
    const int* output_length = (const int*)d_in[1];

    const int B = in_sizes[1];          // 256
    const int Y = in_sizes[0] / B;      // 4096
    const int X = out_size / B - Y;     // 1024

    float* w_out = (float*)d_out;                   // weights_argmax: B*Y
    float* h_out = (float*)d_out + (size_t)B * Y;   // durations:      B*X

    const int threads = 512;
    const size_t smem = (size_t)X * sizeof(int);
    duration_calc_kernel<<<B, threads, smem>>>(duration, output_length,
                                               w_out, h_out, Y, X);
}